// round 7
// baseline (speedup 1.0000x reference)
#include <cuda_runtime.h>
#include <cuda_bf16.h>
#include <mma.h>
#include <cstdint>

using namespace nvcuda;

#define B 512
#define T 256
#define C 384
#define HS 64
#define BT (B * T)

// ---------------- scratch -----------------------------------------------------
__device__ float g_Q[BT * HS];
__device__ float g_K[BT * HS];
__device__ float g_V[BT * HS];

// ---------------- QKV GEMM: WMMA bf16 3-product split, double-buffered --------
// 256 threads = 8 warps (2M x 4N). CTA tile 64x192, BK=32, 12 chunks.
// W converted fp32 -> bf16 hi/lo inline during prefetch (no separate kernel).
// smem per stage: Ahi/Alo [64][40] bf16, Bhi/Blo [32][200] bf16.
static constexpr int A_LD = 40;
static constexpr int B_LD = 200;
static constexpr int OFF_AHI = 0;          // 64*40*2  = 5120
static constexpr int OFF_ALO = 5120;
static constexpr int OFF_BHI = 10240;      // 32*200*2 = 12800
static constexpr int OFF_BLO = 23040;
static constexpr int STAGE   = 35840;
static constexpr int GEMM_SMEM_TOTAL = 2 * STAGE;   // 71680

__device__ __forceinline__ void cvt_store4(char* hiBase, char* loBase,
                                           int elemOff, float4 v)
{
    __nv_bfloat16* ah = (__nv_bfloat16*)hiBase + elemOff;
    __nv_bfloat16* al = (__nv_bfloat16*)loBase + elemOff;
    __nv_bfloat16 h0 = __float2bfloat16(v.x);
    __nv_bfloat16 h1 = __float2bfloat16(v.y);
    __nv_bfloat16 h2 = __float2bfloat16(v.z);
    __nv_bfloat16 h3 = __float2bfloat16(v.w);
    ah[0] = h0; ah[1] = h1; ah[2] = h2; ah[3] = h3;
    al[0] = __float2bfloat16(v.x - __bfloat162float(h0));
    al[1] = __float2bfloat16(v.y - __bfloat162float(h1));
    al[2] = __float2bfloat16(v.z - __bfloat162float(h2));
    al[3] = __float2bfloat16(v.w - __bfloat162float(h3));
}

__global__ __launch_bounds__(256, 2) void qkv_gemm_wmma(
    const float* __restrict__ x,
    const float* __restrict__ Wq,
    const float* __restrict__ Wk,
    const float* __restrict__ Wv)
{
    extern __shared__ char smem[];
    const int tid = threadIdx.x;
    const int wid = tid >> 5;
    const int warp_m = wid >> 2;       // 0..1 -> rows 32*warp_m
    const int warp_n = wid & 3;        // 0..3 -> cols 48*warp_n
    const int rowBase = blockIdx.x * 64;

    // per-thread load coords (fixed for all chunks)
    // x: 64 rows x 8 float4 = 512 -> 2/thread
    const int xr_r[2] = { (tid + 0) >> 3, (tid + 256) >> 3 };
    const int xr_c[2] = { (tid + 0) & 7,  (tid + 256) & 7 };
    // W: 32 rows x 48 float4 = 1536 -> 6/thread
    int wr_r[6], wr_u[6];
    const float* wr_p[6];
#pragma unroll
    for (int t = 0; t < 6; t++) {
        int f = tid + t * 256;
        wr_r[t] = f / 48;
        int u = f - wr_r[t] * 48;
        wr_u[t] = u;
        wr_p[t] = (u < 16) ? Wq : ((u < 32) ? Wk : Wv);
    }

    wmma::fragment<wmma::accumulator, 16, 16, 16, float> acc[2][3];
#pragma unroll
    for (int i = 0; i < 2; i++)
#pragma unroll
        for (int j = 0; j < 3; j++) wmma::fill_fragment(acc[i][j], 0.0f);

    // ---- prologue: chunk 0 into stage 0 ----
    {
        char* st = smem;
#pragma unroll
        for (int t = 0; t < 2; t++) {
            float4 v = *(const float4*)(x + (size_t)(rowBase + xr_r[t]) * C + xr_c[t] * 4);
            cvt_store4(st + OFF_AHI, st + OFF_ALO, xr_r[t] * A_LD + xr_c[t] * 4, v);
        }
#pragma unroll
        for (int t = 0; t < 6; t++) {
            float4 v = *(const float4*)(wr_p[t] + (size_t)wr_r[t] * HS + ((wr_u[t] & 15) << 2));
            cvt_store4(st + OFF_BHI, st + OFF_BLO, wr_r[t] * B_LD + wr_u[t] * 4, v);
        }
    }
    __syncthreads();

    for (int c = 0; c < 12; c++) {
        char* st  = smem + (c & 1) * STAGE;
        char* nst = smem + ((c + 1) & 1) * STAGE;
        const int k1 = (c + 1) * 32;
        const bool more = (c + 1 < 12);

        // global prefetch of chunk c+1
        float4 xr[2];
        float4 wr[6];
        if (more) {
#pragma unroll
            for (int t = 0; t < 2; t++)
                xr[t] = *(const float4*)(x + (size_t)(rowBase + xr_r[t]) * C + k1 + xr_c[t] * 4);
#pragma unroll
            for (int t = 0; t < 6; t++)
                wr[t] = *(const float4*)(wr_p[t] + (size_t)(k1 + wr_r[t]) * HS + ((wr_u[t] & 15) << 2));
        }

        // compute chunk c
        const __nv_bfloat16* Ahi = (const __nv_bfloat16*)(st + OFF_AHI);
        const __nv_bfloat16* Alo = (const __nv_bfloat16*)(st + OFF_ALO);
        const __nv_bfloat16* Bhi = (const __nv_bfloat16*)(st + OFF_BHI);
        const __nv_bfloat16* Blo = (const __nv_bfloat16*)(st + OFF_BLO);
#pragma unroll
        for (int ks = 0; ks < 2; ks++) {
            wmma::fragment<wmma::matrix_a, 16, 16, 16, __nv_bfloat16, wmma::row_major> ah[2], al[2];
#pragma unroll
            for (int i = 0; i < 2; i++) {
                const __nv_bfloat16* pa = Ahi + (warp_m * 32 + i * 16) * A_LD + ks * 16;
                const __nv_bfloat16* pl = Alo + (warp_m * 32 + i * 16) * A_LD + ks * 16;
                wmma::load_matrix_sync(ah[i], pa, A_LD);
                wmma::load_matrix_sync(al[i], pl, A_LD);
            }
#pragma unroll
            for (int j = 0; j < 3; j++) {
                int col = warp_n * 48 + j * 16;
                wmma::fragment<wmma::matrix_b, 16, 16, 16, __nv_bfloat16, wmma::row_major> bh, bl;
                wmma::load_matrix_sync(bh, Bhi + ks * 16 * B_LD + col, B_LD);
                wmma::load_matrix_sync(bl, Blo + ks * 16 * B_LD + col, B_LD);
#pragma unroll
                for (int i = 0; i < 2; i++) {
                    wmma::mma_sync(acc[i][j], ah[i], bh, acc[i][j]);
                    wmma::mma_sync(acc[i][j], ah[i], bl, acc[i][j]);
                    wmma::mma_sync(acc[i][j], al[i], bh, acc[i][j]);
                }
            }
        }

        // store prefetched chunk into the other stage
        if (more) {
#pragma unroll
            for (int t = 0; t < 2; t++)
                cvt_store4(nst + OFF_AHI, nst + OFF_ALO,
                           xr_r[t] * A_LD + xr_c[t] * 4, xr[t]);
#pragma unroll
            for (int t = 0; t < 6; t++)
                cvt_store4(nst + OFF_BHI, nst + OFF_BLO,
                           wr_r[t] * B_LD + wr_u[t] * 4, wr[t]);
        }
        __syncthreads();
    }

    // epilogue
#pragma unroll
    for (int i = 0; i < 2; i++) {
#pragma unroll
        for (int j = 0; j < 3; j++) {
            int col = warp_n * 48 + j * 16;
            float* dst = (col < 64) ? g_Q : ((col < 128) ? g_K : g_V);
            int cc = col & 63;
            int row = rowBase + warp_m * 32 + i * 16;
            wmma::store_matrix_sync(dst + (size_t)row * HS + cc, acc[i][j], HS,
                                    wmma::mem_row_major);
        }
    }
}

// ---------------- causal attention v3: half-split, 512 threads/CTA ------------
// thread = (row tid>>1, half tid&1); each owns 32 dims; dot via shfl.xor(1).
// Loop bound warp-uniform (row|15) so the full-mask shfl is defined.
static constexpr int KROW = 72;
static constexpr int ATTN_SMEM = 2 * T * KROW * 4;   // 147456

__global__ __launch_bounds__(512, 1) void attn(float* __restrict__ out)
{
    extern __shared__ float sm[];
    float* ks = sm;                 // [256][72]
    float* vs = sm + T * KROW;      // [256][72]

    const int b   = blockIdx.x;
    const int tid = threadIdx.x;
    const int row  = tid >> 1;
    const int half = tid & 1;

    {
        const float4* Kg = (const float4*)(g_K + (size_t)b * T * HS);
        const float4* Vg = (const float4*)(g_V + (size_t)b * T * HS);
#pragma unroll
        for (int t = 0; t < 8; t++) {
            int f = tid + t * 512;
            int j = f >> 4;
            int q4 = f & 15;
            int off = j * KROW + ((q4 >= 8) ? (36 + (q4 - 8) * 4) : q4 * 4);
            *(float4*)(ks + off) = Kg[f];
            *(float4*)(vs + off) = Vg[f];
        }
    }
    __syncthreads();

    float q[32];
    {
        const float4* Qg = (const float4*)(g_Q + ((size_t)b * T + row) * HS + half * 32);
#pragma unroll
        for (int h4 = 0; h4 < 8; h4++) {
            float4 v = Qg[h4];
            q[4 * h4 + 0] = v.x; q[4 * h4 + 1] = v.y;
            q[4 * h4 + 2] = v.z; q[4 * h4 + 3] = v.w;
        }
    }

    float acc[32];
#pragma unroll
    for (int h = 0; h < 32; h++) acc[h] = 0.0f;
    float l = 0.0f;
    const float log2e_scale = 1.4426950408889634f * 0.125f;
    const int base = half * 36;
    const int jmax = row | 15;    // warp-uniform upper bound

    for (int j = 0; j <= jmax; j++) {
        const float4* kr = (const float4*)(ks + j * KROW + base);
        float s0 = 0.f, s1 = 0.f, s2 = 0.f, s3 = 0.f;
#pragma unroll
        for (int h4 = 0; h4 < 8; h4++) {
            float4 kv = kr[h4];
            s0 += q[4 * h4 + 0] * kv.x;
            s1 += q[4 * h4 + 1] * kv.y;
            s2 += q[4 * h4 + 2] * kv.z;
            s3 += q[4 * h4 + 3] * kv.w;
        }
        float s = (s0 + s1) + (s2 + s3);
        s += __shfl_xor_sync(0xFFFFFFFFu, s, 1);
        float p = (j <= row) ? exp2f(s * log2e_scale) : 0.0f;
        l += p;
        const float4* vr = (const float4*)(vs + j * KROW + base);
#pragma unroll
        for (int h4 = 0; h4 < 8; h4++) {
            float4 vv = vr[h4];
            acc[4 * h4 + 0] += p * vv.x;
            acc[4 * h4 + 1] += p * vv.y;
            acc[4 * h4 + 2] += p * vv.z;
            acc[4 * h4 + 3] += p * vv.w;
        }
    }

    const float inv = 1.0f / l;
    float4* og = (float4*)(out + ((size_t)b * T + row) * HS + half * 32);
#pragma unroll
    for (int h4 = 0; h4 < 8; h4++) {
        og[h4] = make_float4(acc[4 * h4 + 0] * inv, acc[4 * h4 + 1] * inv,
                             acc[4 * h4 + 2] * inv, acc[4 * h4 + 3] * inv);
    }
}

// ---------------- launch --------------------------------------------------------
extern "C" void kernel_launch(void* const* d_in, const int* in_sizes, int n_in,
                              void* d_out, int out_size)
{
    (void)in_sizes; (void)n_in; (void)out_size;
    const float* x  = (const float*)d_in[0];
    const float* Wq = (const float*)d_in[1];
    const float* Wk = (const float*)d_in[2];
    const float* Wv = (const float*)d_in[3];
    float* out = (float*)d_out;

    cudaFuncSetAttribute(qkv_gemm_wmma, cudaFuncAttributeMaxDynamicSharedMemorySize,
                         GEMM_SMEM_TOTAL);
    qkv_gemm_wmma<<<BT / 64, 256, GEMM_SMEM_TOTAL>>>(x, Wq, Wk, Wv);

    cudaFuncSetAttribute(attn, cudaFuncAttributeMaxDynamicSharedMemorySize,
                         ATTN_SMEM);
    attn<<<B, 512, ATTN_SMEM>>>(out);
}

// round 8
// speedup vs baseline: 1.0497x; 1.0497x over previous
#include <cuda_runtime.h>
#include <cuda_bf16.h>
#include <mma.h>
#include <cstdint>

using namespace nvcuda;

#define B 512
#define T 256
#define C 384
#define HS 64
#define BT (B * T)

// ---------------- scratch -----------------------------------------------------
__device__ float g_Q[BT * HS];
__device__ float g_K[BT * HS];
__device__ float g_V[BT * HS];

// ---------------- QKV GEMM: WMMA bf16 3-product split, double-buffered --------
// 512 threads = 16 warps (4M x 4N). CTA tile 128x192, BK=32, 12 chunks.
// W converted fp32 -> bf16 hi/lo inline during prefetch.
static constexpr int A_LD = 40;
static constexpr int B_LD = 200;
static constexpr int OFF_AHI = 0;          // 128*40*2 = 10240
static constexpr int OFF_ALO = 10240;
static constexpr int OFF_BHI = 20480;      // 32*200*2 = 12800
static constexpr int OFF_BLO = 33280;
static constexpr int STAGE   = 46080;
static constexpr int GEMM_SMEM_TOTAL = 2 * STAGE;   // 92160

__device__ __forceinline__ void cvt_store4(char* hiBase, char* loBase,
                                           int elemOff, float4 v)
{
    __nv_bfloat16* ah = (__nv_bfloat16*)hiBase + elemOff;
    __nv_bfloat16* al = (__nv_bfloat16*)loBase + elemOff;
    __nv_bfloat16 h0 = __float2bfloat16(v.x);
    __nv_bfloat16 h1 = __float2bfloat16(v.y);
    __nv_bfloat16 h2 = __float2bfloat16(v.z);
    __nv_bfloat16 h3 = __float2bfloat16(v.w);
    ah[0] = h0; ah[1] = h1; ah[2] = h2; ah[3] = h3;
    al[0] = __float2bfloat16(v.x - __bfloat162float(h0));
    al[1] = __float2bfloat16(v.y - __bfloat162float(h1));
    al[2] = __float2bfloat16(v.z - __bfloat162float(h2));
    al[3] = __float2bfloat16(v.w - __bfloat162float(h3));
}

__global__ __launch_bounds__(512, 1) void qkv_gemm_wmma(
    const float* __restrict__ x,
    const float* __restrict__ Wq,
    const float* __restrict__ Wk,
    const float* __restrict__ Wv)
{
    extern __shared__ char smem[];
    const int tid = threadIdx.x;
    const int wid = tid >> 5;
    const int warp_m = wid >> 2;       // 0..3 -> rows 32*warp_m
    const int warp_n = wid & 3;        // 0..3 -> cols 48*warp_n
    const int rowBase = blockIdx.x * 128;

    // per-thread load coords (fixed for all chunks)
    // x: 128 rows x 8 float4 = 1024 -> 2/thread
    const int xr_r[2] = { (tid + 0) >> 3, (tid + 512) >> 3 };
    const int xr_c[2] = { (tid + 0) & 7,  (tid + 512) & 7 };
    // W fp32: 32 rows x 48 float4 = 1536 -> 3/thread
    int wr_r[3], wr_u[3];
    const float* wr_p[3];
#pragma unroll
    for (int t = 0; t < 3; t++) {
        int f = tid + t * 512;
        wr_r[t] = f / 48;
        int u = f - wr_r[t] * 48;
        wr_u[t] = u;
        wr_p[t] = (u < 16) ? Wq : ((u < 32) ? Wk : Wv);
    }

    wmma::fragment<wmma::accumulator, 16, 16, 16, float> acc[2][3];
#pragma unroll
    for (int i = 0; i < 2; i++)
#pragma unroll
        for (int j = 0; j < 3; j++) wmma::fill_fragment(acc[i][j], 0.0f);

    // ---- prologue: chunk 0 into stage 0 ----
    {
        char* st = smem;
#pragma unroll
        for (int t = 0; t < 2; t++) {
            float4 v = *(const float4*)(x + (size_t)(rowBase + xr_r[t]) * C + xr_c[t] * 4);
            cvt_store4(st + OFF_AHI, st + OFF_ALO, xr_r[t] * A_LD + xr_c[t] * 4, v);
        }
#pragma unroll
        for (int t = 0; t < 3; t++) {
            float4 v = *(const float4*)(wr_p[t] + (size_t)wr_r[t] * HS + ((wr_u[t] & 15) << 2));
            cvt_store4(st + OFF_BHI, st + OFF_BLO, wr_r[t] * B_LD + wr_u[t] * 4, v);
        }
    }
    __syncthreads();

    for (int c = 0; c < 12; c++) {
        char* st  = smem + (c & 1) * STAGE;
        char* nst = smem + ((c + 1) & 1) * STAGE;
        const int k1 = (c + 1) * 32;
        const bool more = (c + 1 < 12);

        // global prefetch of chunk c+1
        float4 xr[2];
        float4 wr[3];
        if (more) {
#pragma unroll
            for (int t = 0; t < 2; t++)
                xr[t] = *(const float4*)(x + (size_t)(rowBase + xr_r[t]) * C + k1 + xr_c[t] * 4);
#pragma unroll
            for (int t = 0; t < 3; t++)
                wr[t] = *(const float4*)(wr_p[t] + (size_t)(k1 + wr_r[t]) * HS + ((wr_u[t] & 15) << 2));
        }

        // compute chunk c
        const __nv_bfloat16* Ahi = (const __nv_bfloat16*)(st + OFF_AHI);
        const __nv_bfloat16* Alo = (const __nv_bfloat16*)(st + OFF_ALO);
        const __nv_bfloat16* Bhi = (const __nv_bfloat16*)(st + OFF_BHI);
        const __nv_bfloat16* Blo = (const __nv_bfloat16*)(st + OFF_BLO);
#pragma unroll
        for (int ks = 0; ks < 2; ks++) {
            wmma::fragment<wmma::matrix_a, 16, 16, 16, __nv_bfloat16, wmma::row_major> ah[2], al[2];
#pragma unroll
            for (int i = 0; i < 2; i++) {
                const __nv_bfloat16* pa = Ahi + (warp_m * 32 + i * 16) * A_LD + ks * 16;
                const __nv_bfloat16* pl = Alo + (warp_m * 32 + i * 16) * A_LD + ks * 16;
                wmma::load_matrix_sync(ah[i], pa, A_LD);
                wmma::load_matrix_sync(al[i], pl, A_LD);
            }
#pragma unroll
            for (int j = 0; j < 3; j++) {
                int col = warp_n * 48 + j * 16;
                wmma::fragment<wmma::matrix_b, 16, 16, 16, __nv_bfloat16, wmma::row_major> bh, bl;
                wmma::load_matrix_sync(bh, Bhi + ks * 16 * B_LD + col, B_LD);
                wmma::load_matrix_sync(bl, Blo + ks * 16 * B_LD + col, B_LD);
#pragma unroll
                for (int i = 0; i < 2; i++) {
                    wmma::mma_sync(acc[i][j], ah[i], bh, acc[i][j]);
                    wmma::mma_sync(acc[i][j], ah[i], bl, acc[i][j]);
                    wmma::mma_sync(acc[i][j], al[i], bh, acc[i][j]);
                }
            }
        }

        // store prefetched chunk into the other stage
        if (more) {
#pragma unroll
            for (int t = 0; t < 2; t++)
                cvt_store4(nst + OFF_AHI, nst + OFF_ALO,
                           xr_r[t] * A_LD + xr_c[t] * 4, xr[t]);
#pragma unroll
            for (int t = 0; t < 3; t++)
                cvt_store4(nst + OFF_BHI, nst + OFF_BLO,
                           wr_r[t] * B_LD + wr_u[t] * 4, wr[t]);
        }
        __syncthreads();
    }

    // epilogue
#pragma unroll
    for (int i = 0; i < 2; i++) {
#pragma unroll
        for (int j = 0; j < 3; j++) {
            int col = warp_n * 48 + j * 16;
            float* dst = (col < 64) ? g_Q : ((col < 128) ? g_K : g_V);
            int cc = col & 63;
            int row = rowBase + warp_m * 32 + i * 16;
            wmma::store_matrix_sync(dst + (size_t)row * HS + cc, acc[i][j], HS,
                                    wmma::mem_row_major);
        }
    }
}

// ---------------- causal attention v4: half-split + j-unroll-2 ----------------
// thread = (row tid>>1, half tid&1); each owns 32 dims; dot via shfl.xor(1).
// j unrolled by 2: two independent dot/shfl/exp chains overlap in flight.
static constexpr int KROW = 72;
static constexpr int ATTN_SMEM = 2 * T * KROW * 4;   // 147456

__global__ __launch_bounds__(512, 1) void attn(float* __restrict__ out)
{
    extern __shared__ float sm[];
    float* ks = sm;                 // [256][72]
    float* vs = sm + T * KROW;      // [256][72]

    const int b   = blockIdx.x;
    const int tid = threadIdx.x;
    const int row  = tid >> 1;
    const int half = tid & 1;

    {
        const float4* Kg = (const float4*)(g_K + (size_t)b * T * HS);
        const float4* Vg = (const float4*)(g_V + (size_t)b * T * HS);
#pragma unroll
        for (int t = 0; t < 8; t++) {
            int f = tid + t * 512;
            int j = f >> 4;
            int q4 = f & 15;
            int off = j * KROW + ((q4 >= 8) ? (36 + (q4 - 8) * 4) : q4 * 4);
            *(float4*)(ks + off) = Kg[f];
            *(float4*)(vs + off) = Vg[f];
        }
    }
    __syncthreads();

    float q[32];
    {
        const float4* Qg = (const float4*)(g_Q + ((size_t)b * T + row) * HS + half * 32);
#pragma unroll
        for (int h4 = 0; h4 < 8; h4++) {
            float4 v = Qg[h4];
            q[4 * h4 + 0] = v.x; q[4 * h4 + 1] = v.y;
            q[4 * h4 + 2] = v.z; q[4 * h4 + 3] = v.w;
        }
    }

    float acc[32];
#pragma unroll
    for (int h = 0; h < 32; h++) acc[h] = 0.0f;
    float l = 0.0f;
    const float log2e_scale = 1.4426950408889634f * 0.125f;
    const int base = half * 36;
    const int jmax = row | 15;    // warp-uniform; (jmax+1) is a multiple of 16

    for (int j = 0; j <= jmax; j += 2) {
        const float4* kr0 = (const float4*)(ks + (j + 0) * KROW + base);
        const float4* kr1 = (const float4*)(ks + (j + 1) * KROW + base);
        float a0 = 0.f, a1 = 0.f, a2 = 0.f, a3 = 0.f;
        float b0 = 0.f, b1 = 0.f, b2 = 0.f, b3 = 0.f;
#pragma unroll
        for (int h4 = 0; h4 < 8; h4++) {
            float4 ka = kr0[h4];
            float4 kb = kr1[h4];
            a0 += q[4 * h4 + 0] * ka.x;
            a1 += q[4 * h4 + 1] * ka.y;
            a2 += q[4 * h4 + 2] * ka.z;
            a3 += q[4 * h4 + 3] * ka.w;
            b0 += q[4 * h4 + 0] * kb.x;
            b1 += q[4 * h4 + 1] * kb.y;
            b2 += q[4 * h4 + 2] * kb.z;
            b3 += q[4 * h4 + 3] * kb.w;
        }
        float sa = (a0 + a1) + (a2 + a3);
        float sb = (b0 + b1) + (b2 + b3);
        sa += __shfl_xor_sync(0xFFFFFFFFu, sa, 1);
        sb += __shfl_xor_sync(0xFFFFFFFFu, sb, 1);
        float pa = (j + 0 <= row) ? exp2f(sa * log2e_scale) : 0.0f;
        float pb = (j + 1 <= row) ? exp2f(sb * log2e_scale) : 0.0f;
        l += pa + pb;
        const float4* vr0 = (const float4*)(vs + (j + 0) * KROW + base);
        const float4* vr1 = (const float4*)(vs + (j + 1) * KROW + base);
#pragma unroll
        for (int h4 = 0; h4 < 8; h4++) {
            float4 va = vr0[h4];
            float4 vb = vr1[h4];
            acc[4 * h4 + 0] += pa * va.x;
            acc[4 * h4 + 1] += pa * va.y;
            acc[4 * h4 + 2] += pa * va.z;
            acc[4 * h4 + 3] += pa * va.w;
            acc[4 * h4 + 0] += pb * vb.x;
            acc[4 * h4 + 1] += pb * vb.y;
            acc[4 * h4 + 2] += pb * vb.z;
            acc[4 * h4 + 3] += pb * vb.w;
        }
    }

    const float inv = 1.0f / l;
    float4* og = (float4*)(out + ((size_t)b * T + row) * HS + half * 32);
#pragma unroll
    for (int h4 = 0; h4 < 8; h4++) {
        og[h4] = make_float4(acc[4 * h4 + 0] * inv, acc[4 * h4 + 1] * inv,
                             acc[4 * h4 + 2] * inv, acc[4 * h4 + 3] * inv);
    }
}

// ---------------- launch --------------------------------------------------------
extern "C" void kernel_launch(void* const* d_in, const int* in_sizes, int n_in,
                              void* d_out, int out_size)
{
    (void)in_sizes; (void)n_in; (void)out_size;
    const float* x  = (const float*)d_in[0];
    const float* Wq = (const float*)d_in[1];
    const float* Wk = (const float*)d_in[2];
    const float* Wv = (const float*)d_in[3];
    float* out = (float*)d_out;

    cudaFuncSetAttribute(qkv_gemm_wmma, cudaFuncAttributeMaxDynamicSharedMemorySize,
                         GEMM_SMEM_TOTAL);
    qkv_gemm_wmma<<<BT / 128, 512, GEMM_SMEM_TOTAL>>>(x, Wq, Wk, Wv);

    cudaFuncSetAttribute(attn, cudaFuncAttributeMaxDynamicSharedMemorySize,
                         ATTN_SMEM);
    attn<<<B, 512, ATTN_SMEM>>>(out);
}

// round 9
// speedup vs baseline: 1.2052x; 1.1481x over previous
#include <cuda_runtime.h>
#include <cuda_bf16.h>
#include <mma.h>
#include <cstdint>

using namespace nvcuda;

#define B 512
#define T 256
#define C 384
#define HS 64
#define BT (B * T)

// ---------------- scratch -----------------------------------------------------
__device__ float g_Q[BT * HS];
__device__ float g_K[BT * HS];
__device__ float g_V[BT * HS];

// ---------------- QKV GEMM: WMMA bf16 3-product split, double-buffered --------
// (unchanged from round 8)
static constexpr int A_LD = 40;
static constexpr int B_LD = 200;
static constexpr int OFF_AHI = 0;
static constexpr int OFF_ALO = 10240;
static constexpr int OFF_BHI = 20480;
static constexpr int OFF_BLO = 33280;
static constexpr int STAGE   = 46080;
static constexpr int GEMM_SMEM_TOTAL = 2 * STAGE;   // 92160

__device__ __forceinline__ void cvt_store4(char* hiBase, char* loBase,
                                           int elemOff, float4 v)
{
    __nv_bfloat16* ah = (__nv_bfloat16*)hiBase + elemOff;
    __nv_bfloat16* al = (__nv_bfloat16*)loBase + elemOff;
    __nv_bfloat16 h0 = __float2bfloat16(v.x);
    __nv_bfloat16 h1 = __float2bfloat16(v.y);
    __nv_bfloat16 h2 = __float2bfloat16(v.z);
    __nv_bfloat16 h3 = __float2bfloat16(v.w);
    ah[0] = h0; ah[1] = h1; ah[2] = h2; ah[3] = h3;
    al[0] = __float2bfloat16(v.x - __bfloat162float(h0));
    al[1] = __float2bfloat16(v.y - __bfloat162float(h1));
    al[2] = __float2bfloat16(v.z - __bfloat162float(h2));
    al[3] = __float2bfloat16(v.w - __bfloat162float(h3));
}

__global__ __launch_bounds__(512, 1) void qkv_gemm_wmma(
    const float* __restrict__ x,
    const float* __restrict__ Wq,
    const float* __restrict__ Wk,
    const float* __restrict__ Wv)
{
    extern __shared__ char smem[];
    const int tid = threadIdx.x;
    const int wid = tid >> 5;
    const int warp_m = wid >> 2;
    const int warp_n = wid & 3;
    const int rowBase = blockIdx.x * 128;

    const int xr_r[2] = { (tid + 0) >> 3, (tid + 512) >> 3 };
    const int xr_c[2] = { (tid + 0) & 7,  (tid + 512) & 7 };
    int wr_r[3], wr_u[3];
    const float* wr_p[3];
#pragma unroll
    for (int t = 0; t < 3; t++) {
        int f = tid + t * 512;
        wr_r[t] = f / 48;
        int u = f - wr_r[t] * 48;
        wr_u[t] = u;
        wr_p[t] = (u < 16) ? Wq : ((u < 32) ? Wk : Wv);
    }

    wmma::fragment<wmma::accumulator, 16, 16, 16, float> acc[2][3];
#pragma unroll
    for (int i = 0; i < 2; i++)
#pragma unroll
        for (int j = 0; j < 3; j++) wmma::fill_fragment(acc[i][j], 0.0f);

    {
        char* st = smem;
#pragma unroll
        for (int t = 0; t < 2; t++) {
            float4 v = *(const float4*)(x + (size_t)(rowBase + xr_r[t]) * C + xr_c[t] * 4);
            cvt_store4(st + OFF_AHI, st + OFF_ALO, xr_r[t] * A_LD + xr_c[t] * 4, v);
        }
#pragma unroll
        for (int t = 0; t < 3; t++) {
            float4 v = *(const float4*)(wr_p[t] + (size_t)wr_r[t] * HS + ((wr_u[t] & 15) << 2));
            cvt_store4(st + OFF_BHI, st + OFF_BLO, wr_r[t] * B_LD + wr_u[t] * 4, v);
        }
    }
    __syncthreads();

    for (int c = 0; c < 12; c++) {
        char* st  = smem + (c & 1) * STAGE;
        char* nst = smem + ((c + 1) & 1) * STAGE;
        const int k1 = (c + 1) * 32;
        const bool more = (c + 1 < 12);

        float4 xr[2];
        float4 wr[3];
        if (more) {
#pragma unroll
            for (int t = 0; t < 2; t++)
                xr[t] = *(const float4*)(x + (size_t)(rowBase + xr_r[t]) * C + k1 + xr_c[t] * 4);
#pragma unroll
            for (int t = 0; t < 3; t++)
                wr[t] = *(const float4*)(wr_p[t] + (size_t)(k1 + wr_r[t]) * HS + ((wr_u[t] & 15) << 2));
        }

        const __nv_bfloat16* Ahi = (const __nv_bfloat16*)(st + OFF_AHI);
        const __nv_bfloat16* Alo = (const __nv_bfloat16*)(st + OFF_ALO);
        const __nv_bfloat16* Bhi = (const __nv_bfloat16*)(st + OFF_BHI);
        const __nv_bfloat16* Blo = (const __nv_bfloat16*)(st + OFF_BLO);
#pragma unroll
        for (int ks = 0; ks < 2; ks++) {
            wmma::fragment<wmma::matrix_a, 16, 16, 16, __nv_bfloat16, wmma::row_major> ah[2], al[2];
#pragma unroll
            for (int i = 0; i < 2; i++) {
                wmma::load_matrix_sync(ah[i], Ahi + (warp_m * 32 + i * 16) * A_LD + ks * 16, A_LD);
                wmma::load_matrix_sync(al[i], Alo + (warp_m * 32 + i * 16) * A_LD + ks * 16, A_LD);
            }
#pragma unroll
            for (int j = 0; j < 3; j++) {
                int col = warp_n * 48 + j * 16;
                wmma::fragment<wmma::matrix_b, 16, 16, 16, __nv_bfloat16, wmma::row_major> bh, bl;
                wmma::load_matrix_sync(bh, Bhi + ks * 16 * B_LD + col, B_LD);
                wmma::load_matrix_sync(bl, Blo + ks * 16 * B_LD + col, B_LD);
#pragma unroll
                for (int i = 0; i < 2; i++) {
                    wmma::mma_sync(acc[i][j], ah[i], bh, acc[i][j]);
                    wmma::mma_sync(acc[i][j], ah[i], bl, acc[i][j]);
                    wmma::mma_sync(acc[i][j], al[i], bh, acc[i][j]);
                }
            }
        }

        if (more) {
#pragma unroll
            for (int t = 0; t < 2; t++)
                cvt_store4(nst + OFF_AHI, nst + OFF_ALO,
                           xr_r[t] * A_LD + xr_c[t] * 4, xr[t]);
#pragma unroll
            for (int t = 0; t < 3; t++)
                cvt_store4(nst + OFF_BHI, nst + OFF_BLO,
                           wr_r[t] * B_LD + wr_u[t] * 4, wr[t]);
        }
        __syncthreads();
    }

#pragma unroll
    for (int i = 0; i < 2; i++) {
#pragma unroll
        for (int j = 0; j < 3; j++) {
            int col = warp_n * 48 + j * 16;
            float* dst = (col < 64) ? g_Q : ((col < 128) ? g_K : g_V);
            int cc = col & 63;
            int row = rowBase + warp_m * 32 + i * 16;
            wmma::store_matrix_sync(dst + (size_t)row * HS + cc, acc[i][j], HS,
                                    wmma::mem_row_major);
        }
    }
}

// ---------------- attention v5: WMMA flash-style ------------------------------
// Grid (2, 512): CTA = (q-tile of 128 rows, batch). 512 threads = 16 warps.
// Per 64-key tile: S = Q K^T (bf16 3-product split) -> smem fp32 -> exp+mask ->
// P bf16 hi/lo -> O += P V (split), O fragments persist across key tiles.
static constexpr int LDH = 72;                 // padded row (elems)
static constexpr int AOF_QHI = 0;              // 128*72*2 = 18432
static constexpr int AOF_QLO = 18432;
static constexpr int AOF_KHI = 36864;          // 64*72*2 = 9216
static constexpr int AOF_KLO = 46080;
static constexpr int AOF_VHI = 55296;
static constexpr int AOF_VLO = 64512;
static constexpr int AOF_S   = 73728;          // 128*72*4 = 36864
static constexpr int AOF_PHI = 110592;
static constexpr int AOF_PLO = 129024;
static constexpr int AOF_L   = 147456;         // 128*4
static constexpr int ATTN_SMEM = 147968;

__global__ __launch_bounds__(512, 1) void attn_wmma(float* __restrict__ out)
{
    extern __shared__ char smem[];
    __nv_bfloat16* Qhi = (__nv_bfloat16*)(smem + AOF_QHI);
    __nv_bfloat16* Qlo = (__nv_bfloat16*)(smem + AOF_QLO);
    __nv_bfloat16* Khi = (__nv_bfloat16*)(smem + AOF_KHI);
    __nv_bfloat16* Klo = (__nv_bfloat16*)(smem + AOF_KLO);
    __nv_bfloat16* Vhi = (__nv_bfloat16*)(smem + AOF_VHI);
    __nv_bfloat16* Vlo = (__nv_bfloat16*)(smem + AOF_VLO);
    float*         S   = (float*)(smem + AOF_S);
    __nv_bfloat16* Phi = (__nv_bfloat16*)(smem + AOF_PHI);
    __nv_bfloat16* Plo = (__nv_bfloat16*)(smem + AOF_PLO);
    float*         lbuf = (float*)(smem + AOF_L);

    const int qt  = blockIdx.x;        // 0..1
    const int b   = blockIdx.y;        // 0..511
    const int i0  = qt * 128;
    const int tid = threadIdx.x;
    const int wid = tid >> 5;
    const int rt  = wid >> 1;          // warp row-tile 0..7 (16 rows each)
    const int cp  = wid & 1;           // warp col-pair -> cols cp*32

    if (tid < 128) lbuf[tid] = 0.0f;

    // load Q tile [128 x 64] -> bf16 hi/lo
    {
        const float4* Qg = (const float4*)(g_Q + ((size_t)b * T + i0) * HS);
#pragma unroll
        for (int t = 0; t < 4; t++) {
            int f = tid + t * 512;
            int r = f >> 4, c4 = f & 15;
            cvt_store4((char*)Qhi, (char*)Qlo, r * LDH + c4 * 4, Qg[f]);
        }
    }
    __syncthreads();

    wmma::fragment<wmma::accumulator, 16, 16, 16, float> oacc[2];
    wmma::fill_fragment(oacc[0], 0.0f);
    wmma::fill_fragment(oacc[1], 0.0f);

    const float log2e_scale = 1.4426950408889634f * 0.125f;
    const int nkt = qt == 0 ? 2 : 4;
    const int i_glob = i0 + (tid >> 2);
    const int r_exp  = tid >> 2;
    const int cg     = tid & 3;

    for (int kt = 0; kt < nkt; kt++) {
        const int j0 = kt * 64;

        // load K,V tile [64 x 64] -> bf16 hi/lo
        {
            const float4* Kg = (const float4*)(g_K + ((size_t)b * T + j0) * HS);
            const float4* Vg = (const float4*)(g_V + ((size_t)b * T + j0) * HS);
#pragma unroll
            for (int t = 0; t < 2; t++) {
                int f = tid + t * 512;
                int r = f >> 4, c4 = f & 15;
                cvt_store4((char*)Khi, (char*)Klo, r * LDH + c4 * 4, Kg[f]);
                cvt_store4((char*)Vhi, (char*)Vlo, r * LDH + c4 * 4, Vg[f]);
            }
        }
        __syncthreads();

        // ---- S = Q K^T : warp tile = 16 rows x 32 cols (2 frags) ----
#pragma unroll
        for (int f = 0; f < 2; f++) {
            const int n = cp * 32 + f * 16;
            wmma::fragment<wmma::accumulator, 16, 16, 16, float> sacc;
            wmma::fill_fragment(sacc, 0.0f);
#pragma unroll
            for (int ks = 0; ks < 4; ks++) {
                wmma::fragment<wmma::matrix_a, 16, 16, 16, __nv_bfloat16, wmma::row_major> ah, al;
                wmma::fragment<wmma::matrix_b, 16, 16, 16, __nv_bfloat16, wmma::col_major> bh, bl;
                wmma::load_matrix_sync(ah, Qhi + rt * 16 * LDH + ks * 16, LDH);
                wmma::load_matrix_sync(al, Qlo + rt * 16 * LDH + ks * 16, LDH);
                wmma::load_matrix_sync(bh, Khi + n * LDH + ks * 16, LDH);
                wmma::load_matrix_sync(bl, Klo + n * LDH + ks * 16, LDH);
                wmma::mma_sync(sacc, ah, bh, sacc);
                wmma::mma_sync(sacc, ah, bl, sacc);
                wmma::mma_sync(sacc, al, bh, sacc);
            }
            wmma::store_matrix_sync(S + rt * 16 * LDH + n, sacc, LDH,
                                    wmma::mem_row_major);
        }
        __syncthreads();

        // ---- exp + causal mask + row sums + P bf16 split ----
        {
            float* srow = S + r_exp * LDH + cg * 16;
            __nv_bfloat16* ph = Phi + r_exp * LDH + cg * 16;
            __nv_bfloat16* pl = Plo + r_exp * LDH + cg * 16;
            float ps = 0.0f;
#pragma unroll
            for (int c = 0; c < 16; c++) {
                int j = j0 + cg * 16 + c;
                float p = (j <= i_glob) ? exp2f(srow[c] * log2e_scale) : 0.0f;
                ps += p;
                __nv_bfloat16 hi = __float2bfloat16(p);
                ph[c] = hi;
                pl[c] = __float2bfloat16(p - __bfloat162float(hi));
            }
            ps += __shfl_xor_sync(0xFFFFFFFFu, ps, 1);
            ps += __shfl_xor_sync(0xFFFFFFFFu, ps, 2);
            if (cg == 0) lbuf[r_exp] += ps;
        }
        __syncthreads();

        // ---- O += P V ----
#pragma unroll
        for (int ks = 0; ks < 4; ks++) {
            wmma::fragment<wmma::matrix_a, 16, 16, 16, __nv_bfloat16, wmma::row_major> ah, al;
            wmma::load_matrix_sync(ah, Phi + rt * 16 * LDH + ks * 16, LDH);
            wmma::load_matrix_sync(al, Plo + rt * 16 * LDH + ks * 16, LDH);
#pragma unroll
            for (int f = 0; f < 2; f++) {
                const int n = cp * 32 + f * 16;
                wmma::fragment<wmma::matrix_b, 16, 16, 16, __nv_bfloat16, wmma::row_major> bh, bl;
                wmma::load_matrix_sync(bh, Vhi + ks * 16 * LDH + n, LDH);
                wmma::load_matrix_sync(bl, Vlo + ks * 16 * LDH + n, LDH);
                wmma::mma_sync(oacc[f], ah, bh, oacc[f]);
                wmma::mma_sync(oacc[f], ah, bl, oacc[f]);
                wmma::mma_sync(oacc[f], al, bh, oacc[f]);
            }
        }
        __syncthreads();
    }

    // ---- epilogue: normalize + write ----
#pragma unroll
    for (int f = 0; f < 2; f++) {
        const int n = cp * 32 + f * 16;
        wmma::store_matrix_sync(S + rt * 16 * LDH + n, oacc[f], LDH,
                                wmma::mem_row_major);
    }
    __syncthreads();
    {
        const float inv = 1.0f / lbuf[r_exp];
        const float* srow = S + r_exp * LDH + cg * 16;
        float* og = out + ((size_t)b * T + i0 + r_exp) * HS + cg * 16;
#pragma unroll
        for (int c4 = 0; c4 < 4; c4++) {
            float4 v = *(const float4*)(srow + c4 * 4);
            *(float4*)(og + c4 * 4) =
                make_float4(v.x * inv, v.y * inv, v.z * inv, v.w * inv);
        }
    }
}

// ---------------- launch --------------------------------------------------------
extern "C" void kernel_launch(void* const* d_in, const int* in_sizes, int n_in,
                              void* d_out, int out_size)
{
    (void)in_sizes; (void)n_in; (void)out_size;
    const float* x  = (const float*)d_in[0];
    const float* Wq = (const float*)d_in[1];
    const float* Wk = (const float*)d_in[2];
    const float* Wv = (const float*)d_in[3];
    float* out = (float*)d_out;

    cudaFuncSetAttribute(qkv_gemm_wmma, cudaFuncAttributeMaxDynamicSharedMemorySize,
                         GEMM_SMEM_TOTAL);
    qkv_gemm_wmma<<<BT / 128, 512, GEMM_SMEM_TOTAL>>>(x, Wq, Wk, Wv);

    cudaFuncSetAttribute(attn_wmma, cudaFuncAttributeMaxDynamicSharedMemorySize,
                         ATTN_SMEM);
    dim3 agrid(2, B);
    attn_wmma<<<agrid, 512, ATTN_SMEM>>>(out);
}